// round 3
// baseline (speedup 1.0000x reference)
#include <cuda_runtime.h>
#include <cuda_bf16.h>

// iDCT along channel axis == DCT-III:
//   out[b,m,s] = ip[b,0,s] + 2 * sum_{k=1..C-1} ip[b,k,s] * cos(pi*k*(2m+1)/(2C))
// Implemented as per-batch GEMM: Out[256,16384] = M[256x256] * In[256,16384].
// Inner product uses packed fma.rn.f32x2 (FFMA2) to reach full FP32 rate on sm_103a.

#define C_DIM 256
#define HW_DIM (128 * 128)
#define BM 128
#define BN 128
#define BK 8
#define TM 8
#define TN 8

// DCT matrix stored transposed: g_dctMT[k*256 + m] = M[m][k]
__device__ float g_dctMT[C_DIM * C_DIM];

__global__ void init_dct_mt() {
    int k = blockIdx.x;   // 0..255
    int m = threadIdx.x;  // 0..255
    float val;
    if (k == 0) {
        val = 1.0f;
    } else {
        // cos(pi * k * (2m+1) / 512); k*(2m+1) <= 255*511 < 2^24, exact in fp32
        val = 2.0f * cospif((float)(k * (2 * m + 1)) * (1.0f / 512.0f));
    }
    g_dctMT[k * C_DIM + m] = val;
}

__device__ __forceinline__ unsigned long long ffma2(unsigned long long a,
                                                    unsigned long long b,
                                                    unsigned long long c) {
    unsigned long long d;
    asm("fma.rn.f32x2 %0, %1, %2, %3;" : "=l"(d) : "l"(a), "l"(b), "l"(c));
    return d;
}

__device__ __forceinline__ unsigned long long pack2(float x) {
    unsigned long long r;
    asm("mov.b64 %0, {%1, %1};" : "=l"(r) : "f"(x));
    return r;
}

__global__ __launch_bounds__(256, 2)
void idct_gemm_kernel(const float* __restrict__ in, float* __restrict__ out) {
    __shared__ float As[BK][BM];  // As[k][m]
    __shared__ float Bs[BK][BN];  // Bs[k][n]

    const int tid = threadIdx.x;
    const int tx = tid & 15;   // 0..15 -> n micro-tile
    const int ty = tid >> 4;   // 0..15 -> m micro-tile
    const int n0 = blockIdx.x * BN;
    const int m0 = blockIdx.y * BM;
    const size_t batch_off = (size_t)blockIdx.z * C_DIM * HW_DIM;
    const float* inB = in + batch_off;
    float* outB = out + batch_off;

    // cooperative tile-load indexing: 256 threads x float4 = 1024 floats = one 8x128 tile
    const int lrow = tid >> 5;        // 0..7  (k within tile)
    const int lcol = (tid & 31) * 4;  // 0..124

    unsigned long long acc[TM][TN / 2];
#pragma unroll
    for (int i = 0; i < TM; ++i)
#pragma unroll
        for (int j = 0; j < TN / 2; ++j) acc[i][j] = 0ULL;  // (0.0f, 0.0f)

    // prefetch first tile into registers
    float4 av = *reinterpret_cast<const float4*>(&g_dctMT[lrow * C_DIM + m0 + lcol]);
    float4 bv = *reinterpret_cast<const float4*>(&inB[(size_t)lrow * HW_DIM + n0 + lcol]);

#pragma unroll 1
    for (int t = 0; t < C_DIM / BK; ++t) {
        *reinterpret_cast<float4*>(&As[lrow][lcol]) = av;
        *reinterpret_cast<float4*>(&Bs[lrow][lcol]) = bv;
        __syncthreads();

        if (t + 1 < C_DIM / BK) {
            const int k0 = (t + 1) * BK;
            av = *reinterpret_cast<const float4*>(&g_dctMT[(k0 + lrow) * C_DIM + m0 + lcol]);
            bv = *reinterpret_cast<const float4*>(&inB[(size_t)(k0 + lrow) * HW_DIM + n0 + lcol]);
        }

#pragma unroll
        for (int kk = 0; kk < BK; ++kk) {
            float a[TM];
            *reinterpret_cast<float4*>(&a[0]) =
                *reinterpret_cast<const float4*>(&As[kk][ty * TM]);
            *reinterpret_cast<float4*>(&a[4]) =
                *reinterpret_cast<const float4*>(&As[kk][ty * TM + 4]);
            // B fragment read directly as packed f32x2 pairs (adjacent n)
            ulonglong2 b01 = *reinterpret_cast<const ulonglong2*>(&Bs[kk][tx * TN]);
            ulonglong2 b23 = *reinterpret_cast<const ulonglong2*>(&Bs[kk][tx * TN + 4]);
#pragma unroll
            for (int i = 0; i < TM; ++i) {
                unsigned long long ap = pack2(a[i]);
                acc[i][0] = ffma2(ap, b01.x, acc[i][0]);
                acc[i][1] = ffma2(ap, b01.y, acc[i][1]);
                acc[i][2] = ffma2(ap, b23.x, acc[i][2]);
                acc[i][3] = ffma2(ap, b23.y, acc[i][3]);
            }
        }
        __syncthreads();
    }

    // epilogue: each thread owns rows m0+ty*8..+7, cols n0+tx*8..+7 (contiguous)
#pragma unroll
    for (int i = 0; i < TM; ++i) {
        float* op = outB + (size_t)(m0 + ty * TM + i) * HW_DIM + n0 + tx * TN;
#pragma unroll
        for (int j = 0; j < TN / 2; ++j) {
            reinterpret_cast<unsigned long long*>(op)[j] = acc[i][j];
        }
    }
}

extern "C" void kernel_launch(void* const* d_in, const int* in_sizes, int n_in,
                              void* d_out, int out_size) {
    const float* in = (const float*)d_in[0];
    float* out = (float*)d_out;

    const int batches = in_sizes[0] / (C_DIM * HW_DIM);  // = 8

    init_dct_mt<<<C_DIM, C_DIM>>>();

    dim3 grid(HW_DIM / BN, C_DIM / BM, batches);
    idct_gemm_kernel<<<grid, 256>>>(in, out);
}

// round 8
// speedup vs baseline: 1.7391x; 1.7391x over previous
#include <cuda_runtime.h>
#include <cuda_bf16.h>
#include <cstdint>

// iDCT-III along channels == GEMM  Out[256,16384] = M[256,256] * In[256,16384] per batch,
//   M[m,k] = (k==0) ? 1 : 2*cos(pi*k*(2m+1)/512)
// 3-term bf16 split for fp32-class accuracy: Out ~= Ahi*Bhi + Alo*Bhi + Ahi*Blo (fp32 accum).
// tcgen05 is unavailable in this build (ptxas targets sm_103, not sm_103a), so tensor work
// goes through baseline-PTX mma.sync.aligned.m16n8k16 (HMMA) + ldmatrix.trans.

#define C_DIM 256
#define HW_DIM 16384
#define BNT 128   // CTA n-tile
#define BK 32
#define NCHUNK (C_DIM / BK)  // 8

// ---------- A precomputed in mma-fragment order ----------
// g_Afrag[k16 (16)][m_atom (16)][split (2)][lane (32)] : uint4 = 4 a-regs (8 bf16)
__device__ uint4 g_Afrag[16 * 16 * 2 * 32];

__global__ void init_A() {
    int idx = blockIdx.x * 256 + threadIdx.x;  // 16384 entries
    int lane  = idx & 31;
    int split = (idx >> 5) & 1;
    int matom = (idx >> 6) & 15;
    int k16   = idx >> 10;
    int r = lane >> 2;
    int c = (lane & 3) * 2;
    uint32_t w[4];
#pragma unroll
    for (int j = 0; j < 4; ++j) {
        int m  = matom * 16 + r + (j & 1) * 8;
        int k0 = k16 * 16 + c + ((j >> 1) & 1) * 8;
        int k1 = k0 + 1;
        // k*(2m+1) <= 255*511 < 2^24 -> exact in fp32
        float v0 = (k0 == 0) ? 1.0f : 2.0f * cospif((float)(k0 * (2 * m + 1)) * (1.0f / 512.0f));
        float v1 = (k1 == 0) ? 1.0f : 2.0f * cospif((float)(k1 * (2 * m + 1)) * (1.0f / 512.0f));
        __nv_bfloat16 h0 = __float2bfloat16(v0);
        __nv_bfloat16 h1 = __float2bfloat16(v1);
        if (split == 0) {
            w[j] = (uint32_t)__bfloat16_as_ushort(h0) | ((uint32_t)__bfloat16_as_ushort(h1) << 16);
        } else {
            __nv_bfloat16 l0 = __float2bfloat16(v0 - __bfloat162float(h0));
            __nv_bfloat16 l1 = __float2bfloat16(v1 - __bfloat162float(h1));
            w[j] = (uint32_t)__bfloat16_as_ushort(l0) | ((uint32_t)__bfloat16_as_ushort(l1) << 16);
        }
    }
    g_Afrag[idx] = make_uint4(w[0], w[1], w[2], w[3]);
}

// ---------- asm helpers (baseline PTX only) ----------
__device__ __forceinline__ uint32_t smem_u32(const void* p) {
    uint32_t a;
    asm("{ .reg .u64 t; cvta.to.shared.u64 t, %1; cvt.u32.u64 %0, t; }" : "=r"(a) : "l"(p));
    return a;
}
__device__ __forceinline__ void ldsm4t(uint32_t r[4], uint32_t addr) {
    asm volatile("ldmatrix.sync.aligned.m8n8.x4.trans.shared.b16 {%0,%1,%2,%3}, [%4];"
                 : "=r"(r[0]), "=r"(r[1]), "=r"(r[2]), "=r"(r[3]) : "r"(addr));
}
__device__ __forceinline__ void mma_bf16(float c[4], const uint32_t a[4],
                                         uint32_t b0, uint32_t b1) {
    asm volatile(
        "mma.sync.aligned.m16n8k16.row.col.f32.bf16.bf16.f32 "
        "{%0,%1,%2,%3}, {%4,%5,%6,%7}, {%8,%9}, {%0,%1,%2,%3};"
        : "+f"(c[0]), "+f"(c[1]), "+f"(c[2]), "+f"(c[3])
        : "r"(a[0]), "r"(a[1]), "r"(a[2]), "r"(a[3]), "r"(b0), "r"(b1));
}

// SMEM B: [stage 2][split 2][k 32][n 136] bf16; 136*2 = 272B row stride (conflict-free ldmatrix)
#define BROW 136
#define SPLIT_B (BK * BROW * 2)       // 8704 bytes
#define STAGE_B (2 * SPLIT_B)         // 17408 bytes
#define KK_B (16 * BROW * 2)          // 4352 bytes (16 k-rows)

__global__ __launch_bounds__(256)
void idct_mma_kernel(const float* __restrict__ in, float* __restrict__ out) {
    __shared__ __align__(16) __nv_bfloat16 Bs[2][2][BK][BROW];

    const int tid  = threadIdx.x;
    const int wid  = tid >> 5;
    const int lane = tid & 31;
    const int warpM = wid & 1;    // 2 x 64-row m blocks
    const int warpN = wid >> 1;   // 4 x 32-col n blocks
    const int n0 = blockIdx.y * BNT;
    const size_t boff = (size_t)blockIdx.z * C_DIM * HW_DIM;
    const float* inB = in + boff;

    float acc[4][4][4];
#pragma unroll
    for (int i = 0; i < 4; ++i)
#pragma unroll
        for (int j = 0; j < 4; ++j)
#pragma unroll
            for (int q = 0; q < 4; ++q) acc[i][j][q] = 0.0f;

    // ldmatrix per-lane source: sel picks (k-half, n-half) of a 16x16 block
    const int sel  = lane >> 3;
    const int krow = (sel & 1) * 8 + (lane & 7);
    const int ncol = warpN * 32 + ((sel >> 1) & 1) * 8;
    const uint32_t lmbase = smem_u32(&Bs[0][0][krow][ncol]);

    // A fragment base: [k16][matom][split][lane]
    const uint4* Abase =
        g_Afrag + ((size_t)(blockIdx.x * 8 + warpM * 4) * 2) * 32 + lane;
    // strides in uint4: k16 -> 1024, matom -> 64, split -> 32

    // --- B global prefetch (chunk 0): thread covers k = wid + i*8, n quad = lane ---
    float4 bv[4];
#pragma unroll
    for (int i = 0; i < 4; ++i)
        bv[i] = *reinterpret_cast<const float4*>(
            &inB[(size_t)(wid + i * 8) * HW_DIM + n0 + lane * 4]);

    for (int t = 0; t < NCHUNK; ++t) {
        const int s = t & 1;
        // store chunk t (split hi/lo) into stage s
#pragma unroll
        for (int i = 0; i < 4; ++i) {
            const int k = wid + i * 8;
            float4 v = bv[i];
            __nv_bfloat162 h0 = __floats2bfloat162_rn(v.x, v.y);
            __nv_bfloat162 h1 = __floats2bfloat162_rn(v.z, v.w);
            __nv_bfloat162 l0 = __floats2bfloat162_rn(v.x - __low2float(h0), v.y - __high2float(h0));
            __nv_bfloat162 l1 = __floats2bfloat162_rn(v.z - __low2float(h1), v.w - __high2float(h1));
            *reinterpret_cast<uint2*>(&Bs[s][0][k][lane * 4]) =
                make_uint2(*reinterpret_cast<uint32_t*>(&h0), *reinterpret_cast<uint32_t*>(&h1));
            *reinterpret_cast<uint2*>(&Bs[s][1][k][lane * 4]) =
                make_uint2(*reinterpret_cast<uint32_t*>(&l0), *reinterpret_cast<uint32_t*>(&l1));
        }
        __syncthreads();

        if (t + 1 < NCHUNK) {
#pragma unroll
            for (int i = 0; i < 4; ++i)
                bv[i] = *reinterpret_cast<const float4*>(
                    &inB[(size_t)((t + 1) * BK + wid + i * 8) * HW_DIM + n0 + lane * 4]);
        }

        const uint32_t stg = lmbase + s * STAGE_B;
#pragma unroll
        for (int kk = 0; kk < 2; ++kk) {
            const int k16g = t * 2 + kk;
            const uint4* Ak = Abase + (size_t)k16g * 1024;
            uint4 Ahi[4], Alo[4];
#pragma unroll
            for (int ma = 0; ma < 4; ++ma) {
                Ahi[ma] = Ak[ma * 64];
                Alo[ma] = Ak[ma * 64 + 32];
            }
            uint32_t bhi[2][4], blo[2][4];
            const uint32_t kkoff = stg + kk * KK_B;
#pragma unroll
            for (int L = 0; L < 2; ++L) {
                ldsm4t(bhi[L], kkoff + L * 32);            // hi split
                ldsm4t(blo[L], kkoff + SPLIT_B + L * 32);  // lo split
            }
            // term 1: Ahi * Bhi  (16 independent mmas)
#pragma unroll
            for (int ma = 0; ma < 4; ++ma)
#pragma unroll
                for (int na = 0; na < 4; ++na)
                    mma_bf16(acc[ma][na], (const uint32_t*)&Ahi[ma],
                             bhi[na >> 1][(na & 1) * 2], bhi[na >> 1][(na & 1) * 2 + 1]);
            // term 2: Alo * Bhi
#pragma unroll
            for (int ma = 0; ma < 4; ++ma)
#pragma unroll
                for (int na = 0; na < 4; ++na)
                    mma_bf16(acc[ma][na], (const uint32_t*)&Alo[ma],
                             bhi[na >> 1][(na & 1) * 2], bhi[na >> 1][(na & 1) * 2 + 1]);
            // term 3: Ahi * Blo
#pragma unroll
            for (int ma = 0; ma < 4; ++ma)
#pragma unroll
                for (int na = 0; na < 4; ++na)
                    mma_bf16(acc[ma][na], (const uint32_t*)&Ahi[ma],
                             blo[na >> 1][(na & 1) * 2], blo[na >> 1][(na & 1) * 2 + 1]);
        }
        __syncthreads();
    }

    // ---------- epilogue ----------
    float* outB = out + boff;
    const int rbase = blockIdx.x * 128 + warpM * 64 + (lane >> 2);
    const int cbase = n0 + warpN * 32 + (lane & 3) * 2;
#pragma unroll
    for (int ma = 0; ma < 4; ++ma) {
#pragma unroll
        for (int na = 0; na < 4; ++na) {
            float* p = outB + (size_t)(rbase + ma * 16) * HW_DIM + cbase + na * 8;
            *reinterpret_cast<float2*>(p) = make_float2(acc[ma][na][0], acc[ma][na][1]);
            *reinterpret_cast<float2*>(p + 8 * HW_DIM) = make_float2(acc[ma][na][2], acc[ma][na][3]);
        }
    }
}

extern "C" void kernel_launch(void* const* d_in, const int* in_sizes, int n_in,
                              void* d_out, int out_size) {
    const float* in = (const float*)d_in[0];
    float* out = (float*)d_out;
    const int batches = in_sizes[0] / (C_DIM * HW_DIM);  // 8

    init_A<<<64, 256>>>();
    dim3 grid(2, HW_DIM / BNT, batches);  // m fastest -> B-panel L2 reuse between m pair
    idct_mma_kernel<<<grid, 256>>>(in, out);
}